// round 1
// baseline (speedup 1.0000x reference)
#include <cuda_runtime.h>

#define B    8
#define NN   2048
#define FIN  128
#define FOUT 64

// Scratch (no cudaMalloc allowed): Wh [B,N,64], s1/s2 [B,N]
__device__ __align__(16) float g_Wh[B * NN * FOUT];
__device__ __align__(16) float g_s1[B * NN];
__device__ __align__(16) float g_s2[B * NN];

// ---------------------------------------------------------------------------
// Kernel 1: Wh = h @ W^T.  64 rows per CTA, 256 threads, W transposed in smem.
// ---------------------------------------------------------------------------
__global__ __launch_bounds__(256) void wh_kernel(const float* __restrict__ h,
                                                 const float* __restrict__ W) {
    __shared__ float Wt[FIN][FOUT];  // 32 KB, Wt[f][o] = W[o][f]
    int tid = threadIdx.x;
    for (int idx = tid; idx < FIN * FOUT; idx += 256) {
        int f = idx / FOUT, o = idx % FOUT;
        Wt[f][o] = W[o * FIN + f];
    }
    __syncthreads();

    int row0 = blockIdx.x * 64;
    int rg = tid >> 4, cg = tid & 15;
    int r0 = row0 + rg * 4;   // 4 rows per thread
    int c0 = cg * 4;          // 4 cols per thread

    float acc[4][4] = {};
    for (int f = 0; f < FIN; f += 4) {
        float4 wv0 = *(const float4*)&Wt[f + 0][c0];
        float4 wv1 = *(const float4*)&Wt[f + 1][c0];
        float4 wv2 = *(const float4*)&Wt[f + 2][c0];
        float4 wv3 = *(const float4*)&Wt[f + 3][c0];
#pragma unroll
        for (int k = 0; k < 4; k++) {
            float4 hv = *(const float4*)&h[(r0 + k) * FIN + f];
            acc[k][0] += hv.x * wv0.x + hv.y * wv1.x + hv.z * wv2.x + hv.w * wv3.x;
            acc[k][1] += hv.x * wv0.y + hv.y * wv1.y + hv.z * wv2.y + hv.w * wv3.y;
            acc[k][2] += hv.x * wv0.z + hv.y * wv1.z + hv.z * wv2.z + hv.w * wv3.z;
            acc[k][3] += hv.x * wv0.w + hv.y * wv1.w + hv.z * wv2.w + hv.w * wv3.w;
        }
    }
#pragma unroll
    for (int k = 0; k < 4; k++) {
        float4 o4 = make_float4(acc[k][0], acc[k][1], acc[k][2], acc[k][3]);
        *(float4*)&g_Wh[(r0 + k) * FOUT + c0] = o4;
    }
}

// ---------------------------------------------------------------------------
// Kernel 2: s1 = Wh @ a[:64], s2 = Wh @ a[64:]
// ---------------------------------------------------------------------------
__global__ __launch_bounds__(256) void s12_kernel(const float* __restrict__ a) {
    int row = blockIdx.x * 256 + threadIdx.x;  // 16384 rows
    const float4* wrow = (const float4*)&g_Wh[row * FOUT];
    float d1 = 0.f, d2 = 0.f;
#pragma unroll
    for (int c = 0; c < FOUT / 4; c++) {
        float4 w = wrow[c];
        float4 x = *(const float4*)&a[c * 4];
        float4 y = *(const float4*)&a[FOUT + c * 4];
        d1 += w.x * x.x + w.y * x.y + w.z * x.z + w.w * x.w;
        d2 += w.x * y.x + w.y * y.y + w.z * y.z + w.w * y.w;
    }
    g_s1[row] = d1;
    g_s2[row] = d2;
}

// ---------------------------------------------------------------------------
// Kernel 3: fused masked-softmax attention + P@Wh.
// Grid (32, 8): CTA = 64 query rows of one batch. J streamed in tiles of 64.
// No max-subtraction needed: |e| <= ~10 so exp() is fp32-safe; masked -> p=0
// exactly matches exp(-1e9 - m) == 0 in the reference.
// ---------------------------------------------------------------------------
__global__ __launch_bounds__(256) void attn_kernel(const int* __restrict__ adj,
                                                   float* __restrict__ out) {
    __shared__ float Ps[64][64];   // 16 KB  P tile (unnormalized weights)
    __shared__ float Vs[64][64];   // 16 KB  Wh tile
    __shared__ float s1s[64];
    __shared__ float dsum[64];     // running softmax denominators

    int b   = blockIdx.y;
    int i0  = blockIdx.x * 64;
    int tid = threadIdx.x;

    if (tid < 64) {
        s1s[tid]  = g_s1[b * NN + i0 + tid];
        dsum[tid] = 0.f;
    }

    // stage-2 (GEMM) coords: 4x4 register tile
    int rg = tid >> 4, cg = tid & 15;
    int r0 = rg * 4, c0 = cg * 4;
    // stage-1 (P build) coords: lane jq covers 4 j's, iw covers rows {iw+16k}
    int jq = tid & 15, iw = tid >> 4;

    float acc[4][4] = {};

    const int* mrow[4];
#pragma unroll
    for (int k = 0; k < 4; k++)
        mrow[k] = adj + (b * NN + i0 + iw + k * 16) * NN + (jq << 2);
    const float4* wh_b = (const float4*)&g_Wh[b * NN * FOUT];
    const float*  s2b  = &g_s2[b * NN];

    for (int j0 = 0; j0 < NN; j0 += 64) {
        __syncthreads();  // protects Ps/Vs reuse + init writes

        // ---- load V tile (coalesced float4) ----
        for (int idx = tid; idx < 64 * 16; idx += 256) {
            int j = idx >> 4, q = idx & 15;
            ((float4*)&Vs[j][0])[q] = wh_b[(j0 + j) * 16 + q];
        }

        // ---- build P tile + row sums ----
        float4 s2v = *(const float4*)&s2b[j0 + (jq << 2)];
#pragma unroll
        for (int k = 0; k < 4; k++) {
            int i = iw + k * 16;
            float s1v = s1s[i];
            int4 m = *(const int4*)(mrow[k] + j0);
            float e;
            float4 p;
            e = s1v + s2v.x; e = e > 0.f ? e : 0.2f * e; p.x = m.x ? __expf(e) : 0.f;
            e = s1v + s2v.y; e = e > 0.f ? e : 0.2f * e; p.y = m.y ? __expf(e) : 0.f;
            e = s1v + s2v.z; e = e > 0.f ? e : 0.2f * e; p.z = m.z ? __expf(e) : 0.f;
            e = s1v + s2v.w; e = e > 0.f ? e : 0.2f * e; p.w = m.w ? __expf(e) : 0.f;
            *(float4*)&Ps[i][jq << 2] = p;
            float rs = (p.x + p.y) + (p.z + p.w);
            rs += __shfl_xor_sync(0xffffffffu, rs, 8);
            rs += __shfl_xor_sync(0xffffffffu, rs, 4);
            rs += __shfl_xor_sync(0xffffffffu, rs, 2);
            rs += __shfl_xor_sync(0xffffffffu, rs, 1);
            if (jq == 0) dsum[i] += rs;
        }
        __syncthreads();

        // ---- C += P_tile @ V_tile (4x4 per thread, float4 smem traffic) ----
#pragma unroll
        for (int jj = 0; jj < 64; jj += 4) {
            float4 v0 = *(const float4*)&Vs[jj + 0][c0];
            float4 v1 = *(const float4*)&Vs[jj + 1][c0];
            float4 v2 = *(const float4*)&Vs[jj + 2][c0];
            float4 v3 = *(const float4*)&Vs[jj + 3][c0];
#pragma unroll
            for (int k = 0; k < 4; k++) {
                float4 p = *(const float4*)&Ps[r0 + k][jj];
                acc[k][0] += p.x * v0.x + p.y * v1.x + p.z * v2.x + p.w * v3.x;
                acc[k][1] += p.x * v0.y + p.y * v1.y + p.z * v2.y + p.w * v3.y;
                acc[k][2] += p.x * v0.z + p.y * v1.z + p.z * v2.z + p.w * v3.z;
                acc[k][3] += p.x * v0.w + p.y * v1.w + p.z * v2.w + p.w * v3.w;
            }
        }
    }

#pragma unroll
    for (int k = 0; k < 4; k++) {
        float inv = 1.0f / dsum[r0 + k];
        float4 o = make_float4(acc[k][0] * inv, acc[k][1] * inv,
                               acc[k][2] * inv, acc[k][3] * inv);
        *(float4*)&out[(b * NN + i0 + r0 + k) * FOUT + c0] = o;
    }
}

// ---------------------------------------------------------------------------
extern "C" void kernel_launch(void* const* d_in, const int* in_sizes, int n_in,
                              void* d_out, int out_size) {
    const float* h   = (const float*)d_in[0];
    const int*   adj = (const int*)d_in[1];
    const float* W   = (const float*)d_in[2];
    const float* a   = (const float*)d_in[3];
    float* out = (float*)d_out;

    wh_kernel<<<(B * NN) / 64, 256>>>(h, W);
    s12_kernel<<<(B * NN) / 256, 256>>>(a);
    attn_kernel<<<dim3(NN / 64, B), 256>>>(adj, out);
}